// round 13
// baseline (speedup 1.0000x reference)
#include <cuda_runtime.h>

#define NTHREADS 256
#define TS 1028                  // tile row stride
#define ROWS 16

#define SM_TOTAL (16 * TS)       // 16448 floats = 65792 B

typedef unsigned long long u64;
typedef unsigned int u32;

// fragment-packed bf16 split weights: [layer*32+block][cell 16][lane 32] -> {h0,h1,l0,l1}
__device__ uint4 g_w1[2 * 32 * 16 * 32];
__device__ uint4 g_w2[2 * 32 * 16 * 32];

__device__ __forceinline__ u64 pack2(float lo, float hi) {
    u64 r; asm("mov.b64 %0, {%1, %2};" : "=l"(r) : "f"(lo), "f"(hi)); return r;
}
__device__ __forceinline__ void unpack2(u64 v, float& lo, float& hi) {
    asm("mov.b64 {%0, %1}, %2;" : "=f"(lo), "=f"(hi) : "l"(v));
}
__device__ __forceinline__ u32 bpack(float lo, float hi) {
    u32 r; asm("cvt.rn.bf16x2.f32 %0, %1, %2;" : "=r"(r) : "f"(hi), "f"(lo)); return r;
}
__device__ __forceinline__ float blof(u32 w) { return __uint_as_float(w << 16); }
__device__ __forceinline__ float bhif(u32 w) { return __uint_as_float(w & 0xFFFF0000u); }
__device__ __forceinline__ void bsplit2(float x0, float x1, u32& h, u32& l) {
    h = bpack(x0, x1);
    l = bpack(x0 - blof(h), x1 - bhif(h));
}
__device__ __forceinline__ void mma16(float* c, const u32* a, u32 b0, u32 b1) {
    asm volatile(
        "mma.sync.aligned.m16n8k16.row.col.f32.bf16.bf16.f32 "
        "{%0,%1,%2,%3}, {%4,%5,%6,%7}, {%8,%9}, {%0,%1,%2,%3};"
        : "+f"(c[0]), "+f"(c[1]), "+f"(c[2]), "+f"(c[3])
        : "r"(a[0]), "r"(a[1]), "r"(a[2]), "r"(a[3]), "r"(b0), "r"(b1));
}
__device__ __forceinline__ float elu(float v) {
    return v > 0.f ? v : (__expf(v) - 1.f);
}

// ---- prep: split weights into bf16 hi/lo, fragment-packed uint4 cells ----
__global__ void prep_kernel(
    const float* __restrict__ W1a, const float* __restrict__ W2a,
    const float* __restrict__ W1b, const float* __restrict__ W2b)
{
    int id = blockIdx.x * blockDim.x + threadIdx.x;   // 65536 total
    int lane = id & 31;
    int cell = (id >> 5) & 15;
    int b    = (id >> 9) & 31;
    int mat  = (id >> 14) & 1;
    int l    = (id >> 15) & 1;
    int g = lane >> 2, t4 = lane & 3;

    float f00, f01, f10, f11;
    if (mat == 0) {
        int nt = cell >> 1, kt = cell & 1;
        int k0 = kt * 16 + 2 * t4, n = nt * 8 + g;
        const float* W = (l ? W1b : W1a) + b * 2048;
        f00 = W[k0 * 64 + n];       f01 = W[(k0 + 1) * 64 + n];
        f10 = W[(k0 + 8) * 64 + n]; f11 = W[(k0 + 9) * 64 + n];
    } else {
        int nt = cell >> 2, kt = cell & 3;
        int k0 = kt * 16 + 2 * t4, n = nt * 8 + g;
        const float* W = (l ? W2b : W2a) + b * 2048;
        f00 = W[k0 * 32 + n];       f01 = W[(k0 + 1) * 32 + n];
        f10 = W[(k0 + 8) * 32 + n]; f11 = W[(k0 + 9) * 32 + n];
    }
    u32 h0, l0, h1, l1;
    bsplit2(f00, f01, h0, l0);
    bsplit2(f10, f11, h1, l1);
    uint4 v; v.x = h0; v.y = h1; v.z = l0; v.w = l1;
    uint4* dst = mat ? g_w2 : g_w1;
    dst[((l * 32 + b) * 16 + cell) * 32 + lane] = v;
}

// in-place per-row 32x32 block transpose; 8 warps x 2 rows = 16 rows
__device__ __forceinline__ void transpose_tile(float* tile, int warp, int lane) {
    const int a2 = lane >> 3;
    const int B  = lane & 7;
    #pragma unroll
    for (int rr = 0; rr < 2; ++rr) {
        float* row = tile + (warp * 2 + rr) * TS;
        float4 v[2][4];
        #pragma unroll
        for (int h = 0; h < 2; ++h) {
            int A = a2 + 4 * h;
            #pragma unroll
            for (int i = 0; i < 4; ++i)
                v[h][i] = *(const float4*)(row + 32 * (4 * A + i) + 4 * B);
        }
        __syncwarp();
        #pragma unroll
        for (int h = 0; h < 2; ++h) {
            int A = a2 + 4 * h;
            #pragma unroll
            for (int i = 0; i < 4; ++i) {
                float4 t;
                t.x = ((const float*)&v[h][0])[i];
                t.y = ((const float*)&v[h][1])[i];
                t.z = ((const float*)&v[h][2])[i];
                t.w = ((const float*)&v[h][3])[i];
                *(float4*)(row + 32 * (4 * B + i) + 4 * A) = t;
            }
        }
        __syncwarp();
    }
}

__global__ __launch_bounds__(NTHREADS, 3) void mixer_kernel(
    const float* __restrict__ x,
    const float* __restrict__ B1a, const float* __restrict__ B2a,
    const float* __restrict__ B1b, const float* __restrict__ B2b,
    float* __restrict__ out)
{
    extern __shared__ float smem[];
    float* tile = smem;

    const int tid  = threadIdx.x;
    const int warp = tid >> 5;
    const int lane = tid & 31;
    const int g    = lane >> 2;
    const int t4   = lane & 3;
    const long row0 = (long)blockIdx.x * ROWS;

    const float* B1p[2] = {B1a, B1b};
    const float* B2p[2] = {B2a, B2b};

    // ---- load x tile ----
    {
        const float4* src = (const float4*)(x + row0 * 1024);
        #pragma unroll
        for (int it = 0; it < 16; ++it) {
            int i = tid + it * NTHREADS;
            int r = i >> 8, c4 = i & 255;
            *(float4*)(tile + r * TS + c4 * 4) = src[r * 256 + c4];
        }
    }
    __syncthreads();

    #pragma unroll 1
    for (int si = 0; si < 8; ++si) {
        if (si == 4) {                       // layer boundary
            __syncthreads();
            transpose_tile(tile, warp, lane);
            __syncthreads();
        }
        const int layer = si >> 2;
        const int blk   = (si & 3) * 8 + warp;
        const int lb    = layer * 32 + blk;
        const int cbase = blk * 32;

        const uint4* w1q = g_w1 + (size_t)lb * 512 + lane;
        const uint4* w2q = g_w2 + (size_t)lb * 512 + lane;

        // ---- A-fragments: bf16 split of x, rows {g, g+8} ----
        u32 xh[2][4], xl[2][4];
        {
            const float* xr = tile + g * TS + cbase;
            #pragma unroll
            for (int kc = 0; kc < 2; ++kc) {
                int c0 = kc * 16 + 2 * t4;
                float2 v0 = *(const float2*)(xr + c0);
                float2 v1 = *(const float2*)(xr + 8 * TS + c0);
                float2 v2 = *(const float2*)(xr + c0 + 8);
                float2 v3 = *(const float2*)(xr + 8 * TS + c0 + 8);
                bsplit2(v0.x, v0.y, xh[kc][0], xl[kc][0]);
                bsplit2(v1.x, v1.y, xh[kc][1], xl[kc][1]);
                bsplit2(v2.x, v2.y, xh[kc][2], xl[kc][2]);
                bsplit2(v3.x, v3.y, xh[kc][3], xl[kc][3]);
            }
        }

        // ---- c2 accumulators: bias + residual (re-read from tile) ----
        float c2[4][4];
        {
            const u64* b2q = (const u64*)(B2p[layer] + blk * 32);
            const float* resp = tile + g * TS + cbase;
            #pragma unroll
            for (int nt = 0; nt < 4; ++nt) {
                float blo, bhi, r0l, r0h, r1l, r1h;
                unpack2(b2q[nt * 4 + t4], blo, bhi);
                unpack2(*(const u64*)(resp + nt * 8 + 2 * t4), r0l, r0h);
                unpack2(*(const u64*)(resp + 8 * TS + nt * 8 + 2 * t4), r1l, r1h);
                c2[nt][0] = blo + r0l; c2[nt][1] = bhi + r0h;
                c2[nt][2] = blo + r1l; c2[nt][3] = bhi + r1h;
            }
        }

        const u64* b1q = (const u64*)(B1p[layer] + blk * 64);

        // ---- fused per-k-chunk: mm1 (hidden 16kt..16kt+15) -> ELU -> mm2 partial ----
        #pragma unroll
        for (int kt = 0; kt < 4; ++kt) {
            uint4 W10 = w1q[(4 * kt + 0) * 32];
            uint4 W11 = w1q[(4 * kt + 1) * 32];
            uint4 W12 = w1q[(4 * kt + 2) * 32];
            uint4 W13 = w1q[(4 * kt + 3) * 32];

            float c1[2][4];
            {
                float blo, bhi;
                unpack2(b1q[(2 * kt) * 4 + t4], blo, bhi);
                c1[0][0] = blo; c1[0][1] = bhi; c1[0][2] = blo; c1[0][3] = bhi;
                unpack2(b1q[(2 * kt + 1) * 4 + t4], blo, bhi);
                c1[1][0] = blo; c1[1][1] = bhi; c1[1][2] = blo; c1[1][3] = bhi;
            }
            mma16(c1[0], xh[0], W10.x, W10.y);
            mma16(c1[1], xh[0], W12.x, W12.y);
            mma16(c1[0], xl[0], W10.x, W10.y);
            mma16(c1[1], xl[0], W12.x, W12.y);
            mma16(c1[0], xh[0], W10.z, W10.w);
            mma16(c1[1], xh[0], W12.z, W12.w);
            mma16(c1[0], xh[1], W11.x, W11.y);
            mma16(c1[1], xh[1], W13.x, W13.y);
            mma16(c1[0], xl[1], W11.x, W11.y);
            mma16(c1[1], xl[1], W13.x, W13.y);
            mma16(c1[0], xh[1], W11.z, W11.w);
            mma16(c1[1], xh[1], W13.z, W13.w);

            // ELU + split -> mm2 A-fragments for this kt
            u32 a2h[4], a2l[4];
            {
                float e0 = elu(c1[0][0]), e1 = elu(c1[0][1]);
                float e2 = elu(c1[0][2]), e3 = elu(c1[0][3]);
                float e4 = elu(c1[1][0]), e5 = elu(c1[1][1]);
                float e6 = elu(c1[1][2]), e7 = elu(c1[1][3]);
                bsplit2(e0, e1, a2h[0], a2l[0]);
                bsplit2(e2, e3, a2h[1], a2l[1]);
                bsplit2(e4, e5, a2h[2], a2l[2]);
                bsplit2(e6, e7, a2h[3], a2l[3]);
            }

            // mm2 partial for this k-chunk
            #pragma unroll
            for (int nt = 0; nt < 4; ++nt) {
                uint4 W2 = w2q[(nt * 4 + kt) * 32];
                mma16(c2[nt], a2h, W2.x, W2.y);
                mma16(c2[nt], a2l, W2.x, W2.y);
                mma16(c2[nt], a2h, W2.z, W2.w);
            }
        }

        // ---- writeback ----
        {
            float* resp = tile + g * TS + cbase;
            #pragma unroll
            for (int nt = 0; nt < 4; ++nt) {
                *(u64*)(resp + nt * 8 + 2 * t4)          = pack2(c2[nt][0], c2[nt][1]);
                *(u64*)(resp + 8 * TS + nt * 8 + 2 * t4) = pack2(c2[nt][2], c2[nt][3]);
            }
        }
    }

    __syncthreads();
    transpose_tile(tile, warp, lane);        // undo layer-1 permutation
    __syncthreads();

    // ---- store output ----
    {
        float4* dst = (float4*)(out + row0 * 1024);
        #pragma unroll
        for (int it = 0; it < 16; ++it) {
            int i = tid + it * NTHREADS;
            int r = i >> 8, c4 = i & 255;
            dst[r * 256 + c4] = *(const float4*)(tile + r * TS + c4 * 4);
        }
    }
}

extern "C" void kernel_launch(void* const* d_in, const int* in_sizes, int n_in,
                              void* d_out, int out_size) {
    const float* x   = (const float*)d_in[0];
    const float* W1a = (const float*)d_in[1];
    const float* B1a = (const float*)d_in[2];
    const float* W2a = (const float*)d_in[3];
    const float* B2a = (const float*)d_in[4];
    const float* W1b = (const float*)d_in[5];
    const float* B1b = (const float*)d_in[6];
    const float* W2b = (const float*)d_in[7];
    const float* B2b = (const float*)d_in[8];
    float* out = (float*)d_out;

    int rows = in_sizes[0] / 1024;
    int grid = rows / ROWS;                    // 1024

    size_t smem_bytes = (size_t)SM_TOTAL * sizeof(float);   // 65792 B
    static int configured = -1;
    if (configured < 0) {
        cudaFuncSetAttribute(mixer_kernel,
                             cudaFuncAttributeMaxDynamicSharedMemorySize,
                             (int)smem_bytes);
        configured = 1;
    }

    prep_kernel<<<256, 256>>>(W1a, W2a, W1b, W2b);
    mixer_kernel<<<grid, NTHREADS, smem_bytes>>>(
        x, B1a, B2a, B1b, B2b, out);
}

// round 14
// speedup vs baseline: 1.1164x; 1.1164x over previous
#include <cuda_runtime.h>

#define NTHREADS 256
#define TS 1028                  // tile row stride
#define ROWS 16

#define SM_TOTAL (16 * TS)       // 16448 floats = 65792 B

typedef unsigned long long u64;
typedef unsigned int u32;

// fragment-packed bf16 split weights: [layer*32+block][cell 16][lane 32] -> {h0,h1,l0,l1}
__device__ uint4 g_w1[2 * 32 * 16 * 32];
__device__ uint4 g_w2[2 * 32 * 16 * 32];

__device__ __forceinline__ u64 pack2(float lo, float hi) {
    u64 r; asm("mov.b64 %0, {%1, %2};" : "=l"(r) : "f"(lo), "f"(hi)); return r;
}
__device__ __forceinline__ void unpack2(u64 v, float& lo, float& hi) {
    asm("mov.b64 {%0, %1}, %2;" : "=f"(lo), "=f"(hi) : "l"(v));
}
__device__ __forceinline__ u32 bpack(float lo, float hi) {
    u32 r; asm("cvt.rn.bf16x2.f32 %0, %1, %2;" : "=r"(r) : "f"(hi), "f"(lo)); return r;
}
__device__ __forceinline__ float blof(u32 w) { return __uint_as_float(w << 16); }
__device__ __forceinline__ float bhif(u32 w) { return __uint_as_float(w & 0xFFFF0000u); }
__device__ __forceinline__ void bsplit2(float x0, float x1, u32& h, u32& l) {
    h = bpack(x0, x1);
    l = bpack(x0 - blof(h), x1 - bhif(h));
}
__device__ __forceinline__ void mma16(float* c, const u32* a, u32 b0, u32 b1) {
    asm volatile(
        "mma.sync.aligned.m16n8k16.row.col.f32.bf16.bf16.f32 "
        "{%0,%1,%2,%3}, {%4,%5,%6,%7}, {%8,%9}, {%0,%1,%2,%3};"
        : "+f"(c[0]), "+f"(c[1]), "+f"(c[2]), "+f"(c[3])
        : "r"(a[0]), "r"(a[1]), "r"(a[2]), "r"(a[3]), "r"(b0), "r"(b1));
}
__device__ __forceinline__ float elu(float v) {
    return v > 0.f ? v : (__expf(v) - 1.f);
}

// ---- prep: split weights into bf16 hi/lo, fragment-packed uint4 cells ----
__global__ void prep_kernel(
    const float* __restrict__ W1a, const float* __restrict__ W2a,
    const float* __restrict__ W1b, const float* __restrict__ W2b)
{
    int id = blockIdx.x * blockDim.x + threadIdx.x;   // 65536 total
    int lane = id & 31;
    int cell = (id >> 5) & 15;
    int b    = (id >> 9) & 31;
    int mat  = (id >> 14) & 1;
    int l    = (id >> 15) & 1;
    int g = lane >> 2, t4 = lane & 3;

    float f00, f01, f10, f11;
    if (mat == 0) {
        int nt = cell >> 1, kt = cell & 1;
        int k0 = kt * 16 + 2 * t4, n = nt * 8 + g;
        const float* W = (l ? W1b : W1a) + b * 2048;
        f00 = W[k0 * 64 + n];       f01 = W[(k0 + 1) * 64 + n];
        f10 = W[(k0 + 8) * 64 + n]; f11 = W[(k0 + 9) * 64 + n];
    } else {
        int nt = cell >> 2, kt = cell & 3;
        int k0 = kt * 16 + 2 * t4, n = nt * 8 + g;
        const float* W = (l ? W2b : W2a) + b * 2048;
        f00 = W[k0 * 32 + n];       f01 = W[(k0 + 1) * 32 + n];
        f10 = W[(k0 + 8) * 32 + n]; f11 = W[(k0 + 9) * 32 + n];
    }
    u32 h0, l0, h1, l1;
    bsplit2(f00, f01, h0, l0);
    bsplit2(f10, f11, h1, l1);
    uint4 v; v.x = h0; v.y = h1; v.z = l0; v.w = l1;
    uint4* dst = mat ? g_w2 : g_w1;
    dst[((l * 32 + b) * 16 + cell) * 32 + lane] = v;
}

// in-place per-row 32x32 block transpose; 8 warps x 2 rows
__device__ __forceinline__ void transpose_tile(float* tile, int warp, int lane) {
    const int a2 = lane >> 3;
    const int B  = lane & 7;
    #pragma unroll
    for (int rr = 0; rr < 2; ++rr) {
        float* row = tile + (warp * 2 + rr) * TS;
        float4 v[2][4];
        #pragma unroll
        for (int h = 0; h < 2; ++h) {
            int A = a2 + 4 * h;
            #pragma unroll
            for (int i = 0; i < 4; ++i)
                v[h][i] = *(const float4*)(row + 32 * (4 * A + i) + 4 * B);
        }
        __syncwarp();
        #pragma unroll
        for (int h = 0; h < 2; ++h) {
            int A = a2 + 4 * h;
            #pragma unroll
            for (int i = 0; i < 4; ++i) {
                float4 t;
                t.x = ((const float*)&v[h][0])[i];
                t.y = ((const float*)&v[h][1])[i];
                t.z = ((const float*)&v[h][2])[i];
                t.w = ((const float*)&v[h][3])[i];
                *(float4*)(row + 32 * (4 * B + i) + 4 * A) = t;
            }
        }
        __syncwarp();
    }
}

__global__ __launch_bounds__(NTHREADS, 2) void mixer_kernel(
    const float* __restrict__ x,
    const float* __restrict__ B1a, const float* __restrict__ B2a,
    const float* __restrict__ B1b, const float* __restrict__ B2b,
    float* __restrict__ out)
{
    extern __shared__ float smem[];
    float* tile = smem;

    const int tid  = threadIdx.x;
    const int warp = tid >> 5;
    const int lane = tid & 31;
    const int g    = lane >> 2;
    const int t4   = lane & 3;
    const long row0 = (long)blockIdx.x * ROWS;

    const float* B1p[2] = {B1a, B1b};
    const float* B2p[2] = {B2a, B2b};

    // ---- load x tile ----
    {
        const float4* src = (const float4*)(x + row0 * 1024);
        #pragma unroll
        for (int it = 0; it < 16; ++it) {
            int i = tid + it * NTHREADS;
            int r = i >> 8, c4 = i & 255;
            *(float4*)(tile + r * TS + c4 * 4) = src[r * 256 + c4];
        }
    }
    __syncthreads();

    #pragma unroll 1
    for (int si = 0; si < 8; ++si) {
        if (si == 4) {                       // layer boundary
            __syncthreads();
            transpose_tile(tile, warp, lane);
            __syncthreads();
        }
        const int layer = si >> 2;
        const int blk   = (si & 3) * 8 + warp;
        const int lb    = layer * 32 + blk;
        const int cbase = blk * 32;

        const uint4* w1q = g_w1 + (size_t)lb * 512 + lane;
        const uint4* w2q = g_w2 + (size_t)lb * 512 + lane;

        // ---- A-fragments: bf16 split of x, rows {g, g+8} ----
        u32 xh[2][4], xl[2][4];
        {
            const float* xr = tile + g * TS + cbase;
            #pragma unroll
            for (int kc = 0; kc < 2; ++kc) {
                int c0 = kc * 16 + 2 * t4;
                float2 v0 = *(const float2*)(xr + c0);
                float2 v1 = *(const float2*)(xr + 8 * TS + c0);
                float2 v2 = *(const float2*)(xr + c0 + 8);
                float2 v3 = *(const float2*)(xr + 8 * TS + c0 + 8);
                bsplit2(v0.x, v0.y, xh[kc][0], xl[kc][0]);
                bsplit2(v1.x, v1.y, xh[kc][1], xl[kc][1]);
                bsplit2(v2.x, v2.y, xh[kc][2], xl[kc][2]);
                bsplit2(v3.x, v3.y, xh[kc][3], xl[kc][3]);
            }
        }

        // ---- matmul1: 16 rows x 64 hidden (6-deep chains, 8-way ILP) ----
        float c1[8][4];
        {
            const u64* b1q = (const u64*)(B1p[layer] + blk * 64);
            #pragma unroll
            for (int nt = 0; nt < 8; ++nt) {
                float blo, bhi;
                unpack2(b1q[nt * 4 + t4], blo, bhi);
                c1[nt][0] = blo; c1[nt][1] = bhi; c1[nt][2] = blo; c1[nt][3] = bhi;
            }
        }
        #pragma unroll
        for (int nt = 0; nt < 8; ++nt) {
            uint4 B0 = w1q[(nt * 2 + 0) * 32];
            uint4 B1 = w1q[(nt * 2 + 1) * 32];
            mma16(c1[nt], xh[0], B0.x, B0.y);
            mma16(c1[nt], xl[0], B0.x, B0.y);
            mma16(c1[nt], xh[0], B0.z, B0.w);
            mma16(c1[nt], xh[1], B1.x, B1.y);
            mma16(c1[nt], xl[1], B1.x, B1.y);
            mma16(c1[nt], xh[1], B1.z, B1.w);
        }

        // ---- ELU in registers, rebuild mm2 A-fragments directly ----
        u32 a2h[4][4], a2l[4][4];
        #pragma unroll
        for (int nt = 0; nt < 8; ++nt) {
            c1[nt][0] = elu(c1[nt][0]); c1[nt][1] = elu(c1[nt][1]);
            c1[nt][2] = elu(c1[nt][2]); c1[nt][3] = elu(c1[nt][3]);
        }
        #pragma unroll
        for (int kt = 0; kt < 4; ++kt) {
            bsplit2(c1[2*kt][0],   c1[2*kt][1],   a2h[kt][0], a2l[kt][0]);
            bsplit2(c1[2*kt][2],   c1[2*kt][3],   a2h[kt][1], a2l[kt][1]);
            bsplit2(c1[2*kt+1][0], c1[2*kt+1][1], a2h[kt][2], a2l[kt][2]);
            bsplit2(c1[2*kt+1][2], c1[2*kt+1][3], a2h[kt][3], a2l[kt][3]);
        }

        // ---- matmul2: dual accumulator chains (6-deep, 8-way ILP) ----
        float c2e[4][4], c2o[4][4];
        {
            const u64* b2q = (const u64*)(B2p[layer] + blk * 32);
            const float* resp = tile + g * TS + cbase;
            #pragma unroll
            for (int nt = 0; nt < 4; ++nt) {
                float blo, bhi, r0l, r0h, r1l, r1h;
                unpack2(b2q[nt * 4 + t4], blo, bhi);
                unpack2(*(const u64*)(resp + nt * 8 + 2 * t4), r0l, r0h);
                unpack2(*(const u64*)(resp + 8 * TS + nt * 8 + 2 * t4), r1l, r1h);
                c2e[nt][0] = blo + r0l; c2e[nt][1] = bhi + r0h;
                c2e[nt][2] = blo + r1l; c2e[nt][3] = bhi + r1h;
                c2o[nt][0] = 0.f; c2o[nt][1] = 0.f;
                c2o[nt][2] = 0.f; c2o[nt][3] = 0.f;
            }
        }
        #pragma unroll
        for (int kp = 0; kp < 2; ++kp) {
            const int ke = 2 * kp;       // even chain: kt = 0, 2
            const int ko = 2 * kp + 1;   // odd  chain: kt = 1, 3
            #pragma unroll
            for (int nt = 0; nt < 4; ++nt) {
                uint4 We = w2q[(nt * 4 + ke) * 32];
                uint4 Wo = w2q[(nt * 4 + ko) * 32];
                mma16(c2e[nt], a2h[ke], We.x, We.y);
                mma16(c2o[nt], a2h[ko], Wo.x, Wo.y);
                mma16(c2e[nt], a2l[ke], We.x, We.y);
                mma16(c2o[nt], a2l[ko], Wo.x, Wo.y);
                mma16(c2e[nt], a2h[ke], We.z, We.w);
                mma16(c2o[nt], a2h[ko], Wo.z, Wo.w);
            }
        }

        // ---- merge chains + writeback ----
        {
            float* resp = tile + g * TS + cbase;
            #pragma unroll
            for (int nt = 0; nt < 4; ++nt) {
                float o0 = c2e[nt][0] + c2o[nt][0];
                float o1 = c2e[nt][1] + c2o[nt][1];
                float o2 = c2e[nt][2] + c2o[nt][2];
                float o3 = c2e[nt][3] + c2o[nt][3];
                *(u64*)(resp + nt * 8 + 2 * t4)          = pack2(o0, o1);
                *(u64*)(resp + 8 * TS + nt * 8 + 2 * t4) = pack2(o2, o3);
            }
        }
    }

    __syncthreads();
    transpose_tile(tile, warp, lane);        // undo layer-1 permutation
    __syncthreads();

    // ---- store output ----
    {
        float4* dst = (float4*)(out + row0 * 1024);
        #pragma unroll
        for (int it = 0; it < 16; ++it) {
            int i = tid + it * NTHREADS;
            int r = i >> 8, c4 = i & 255;
            dst[r * 256 + c4] = *(const float4*)(tile + r * TS + c4 * 4);
        }
    }
}

extern "C" void kernel_launch(void* const* d_in, const int* in_sizes, int n_in,
                              void* d_out, int out_size) {
    const float* x   = (const float*)d_in[0];
    const float* W1a = (const float*)d_in[1];
    const float* B1a = (const float*)d_in[2];
    const float* W2a = (const float*)d_in[3];
    const float* B2a = (const float*)d_in[4];
    const float* W1b = (const float*)d_in[5];
    const float* B1b = (const float*)d_in[6];
    const float* W2b = (const float*)d_in[7];
    const float* B2b = (const float*)d_in[8];
    float* out = (float*)d_out;

    int rows = in_sizes[0] / 1024;
    int grid = rows / ROWS;                    // 1024

    size_t smem_bytes = (size_t)SM_TOTAL * sizeof(float);   // 65792 B
    static int configured = -1;
    if (configured < 0) {
        cudaFuncSetAttribute(mixer_kernel,
                             cudaFuncAttributeMaxDynamicSharedMemorySize,
                             (int)smem_bytes);
        configured = 1;
    }

    prep_kernel<<<256, 256>>>(W1a, W2a, W1b, W2b);
    mixer_kernel<<<grid, NTHREADS, smem_bytes>>>(
        x, B1a, B2a, B1b, B2b, out);
}